// round 11
// baseline (speedup 1.0000x reference)
#include <cuda_runtime.h>
#include <float.h>

// ---------------------------------------------------------------------------
// PointSIFT select_cube + group — SINGLE fused kernel.
//   Blocks 0..B-1: build counting-sort grid (10^3 cells, cell == radius) for
//     their batch: smem histogram -> block scan -> scatter to g_sorted;
//     publish with threadfence + flag.
//   All blocks: spin-wait on flag (build blocks are wave-1-first by CLC
//     order and the whole grid is one wave at 8 blocks/SM -> no deadlock),
//     then run the R8-proven search+gather:
//       search: 8 queries/block, each query served by TWO 16-lane strips in
//         paired warps (z-spans split by parity); winners via block-smem
//         atomicMin on 64-bit (dist_bits<<32 | j) keys (exact reference
//         semantics: unfused fp32 dist, min-dist then min-j).
//       gather: warp q owns query q; float4 feature loads staged in smem,
//         write-out as aligned float4 stores.
//   Last retiring block resets the flags (graph-replay safe).
//
// Output layout (float32, reference return order):
//   [0 .. BN*8*3)             grouped_xyz   [B,N,8,3]
//   [.. +BN*8*(3+C))          grouped_points[B,N,8,3+C]
//   [.. +BN*8)                idx (int32 cast to float) [B,N,8]
// ---------------------------------------------------------------------------

#define GRIDR   10
#define NCELL   (GRIDR*GRIDR*GRIDR)   // 1000
#define BMAX    2
#define NMAX    4096
#define PRADIUS 0.1f
#define QPB     8                     // queries per block == warps per block
#define CFEAT   64
#define FROW    (3 + CFEAT)           // 67
#define GPROW   (8 * FROW)            // 536 floats per query row

__device__ int    g_start [BMAX * (NCELL + 1)];
__device__ float4 g_sorted[BMAX * NMAX];   // x,y,z, w = bitcast(orig index)
__device__ int    g_flag   = 0;            // batches built (reset each launch)
__device__ int    g_retire = 0;            // blocks retired (reset each launch)

__device__ __forceinline__ int cell_of(float x, float y, float z) {
    int cx = (int)(x * 10.0f); cx = min(max(cx, 0), GRIDR - 1);
    int cy = (int)(y * 10.0f); cy = min(max(cy, 0), GRIDR - 1);
    int cz = (int)(z * 10.0f); cz = min(max(cz, 0), GRIDR - 1);
    return (cx * GRIDR + cy) * GRIDR + cz;
}

__global__ __launch_bounds__(QPB * 32)
void k_fused(const float* __restrict__ xyz,
             const float* __restrict__ pts,
             float* __restrict__ gxyz,
             float* __restrict__ gp,
             float* __restrict__ idx_f,
             int B, int N) {
    // ---- shared memory ----
    __shared__ int                s_cnt [1024];       // hist -> cursors
    __shared__ int                s_wsum[8];
    __shared__ unsigned long long s_key [QPB][8];
    __shared__ int                s_jj  [QPB][8];
    __shared__ alignas(16) float  s_stage[QPB][GPROW];
    __shared__ alignas(16) float  s_gx   [QPB][24];

    const int tid  = threadIdx.x;
    const int wd   = tid >> 5;
    const int lane = tid & 31;
    const int lid  = lane;

    // ================= build phase (blocks 0..B-1) =================
    if (blockIdx.x < (unsigned)B) {
        const int bb = blockIdx.x;
        const float* xb = xyz + (size_t)bb * N * 3;

        // zero 1024 virtual cells
        #pragma unroll
        for (int c = tid; c < 1024; c += QPB * 32) s_cnt[c] = 0;
        __syncthreads();

        // pass 1: histogram (re-read xyz in pass 2 to keep regs low)
        for (int i = tid; i < N; i += QPB * 32) {
            float x = xb[3 * i + 0], y = xb[3 * i + 1], z = xb[3 * i + 2];
            atomicAdd(&s_cnt[cell_of(x, y, z)], 1);
        }
        __syncthreads();

        // block scan: thread owns 4 contiguous cells
        int c0 = tid * 4;
        int a0 = s_cnt[c0], a1 = s_cnt[c0 + 1],
            a2 = s_cnt[c0 + 2], a3 = s_cnt[c0 + 3];
        int tsum = a0 + a1 + a2 + a3;
        int x = tsum;
        #pragma unroll
        for (int off = 1; off < 32; off <<= 1) {
            int t = __shfl_up_sync(0xFFFFFFFFu, x, off);
            if (lid >= off) x += t;
        }
        if (lid == 31) s_wsum[wd] = x;
        __syncthreads();
        if (wd == 0 && lid < 8) {
            int y = s_wsum[lid];
            #pragma unroll
            for (int off = 1; off < 8; off <<= 1) {
                int t = __shfl_up_sync(0x000000FFu, y, off);
                if (lid >= off) y += t;
            }
            s_wsum[lid] = y;
        }
        __syncthreads();
        int base = x - tsum + (wd > 0 ? s_wsum[wd - 1] : 0);  // excl prefix

        int e0 = base, e1 = base + a0, e2 = e1 + a1, e3 = e2 + a2;
        int gsb = bb * (NCELL + 1);
        if (c0 + 0 < NCELL) { g_start[gsb + c0 + 0] = e0; }
        if (c0 + 1 < NCELL) { g_start[gsb + c0 + 1] = e1; }
        if (c0 + 2 < NCELL) { g_start[gsb + c0 + 2] = e2; }
        if (c0 + 3 < NCELL) { g_start[gsb + c0 + 3] = e3; }
        if (c0 == NCELL)    { g_start[gsb + NCELL]  = e0; }   // total = N
        __syncthreads();
        // overwrite s_cnt with cursors
        s_cnt[c0 + 0] = e0; s_cnt[c0 + 1] = e1;
        s_cnt[c0 + 2] = e2; s_cnt[c0 + 3] = e3;
        __syncthreads();

        // pass 2: scatter
        float4* dst = g_sorted + (size_t)bb * NMAX;
        for (int i = tid; i < N; i += QPB * 32) {
            float px = xb[3 * i + 0], py = xb[3 * i + 1], pz = xb[3 * i + 2];
            int c = cell_of(px, py, pz);
            int pos = atomicAdd(&s_cnt[c], 1);
            dst[pos] = make_float4(px, py, pz, __int_as_float(i));
        }
        __threadfence();
        __syncthreads();
        if (tid == 0) atomicAdd(&g_flag, 1);
    }

    // ================= wait for both builds =================
    if (tid == 0) {
        while (atomicAdd(&g_flag, 0) < B) __nanosleep(64);
    }
    __syncthreads();
    __threadfence();   // acquire: order g_sorted/g_start reads after flag

    // ================= search phase (R8) =================
    const int w      = wd;
    const int h      = lane >> 4;            // half-warp id
    const int lane16 = lane & 15;
    const int strip  = w & 1;                // span-parity strip
    const int qb     = (w & ~1) + h;         // query slot in block (0..7)
    const int w0b    = blockIdx.x * QPB;     // first global query of block

    const int b  = w0b / N;                  // block never straddles a batch
    const int i0 = w0b - b * N;
    const float* xb = xyz + (size_t)b * N * 3;

    if (tid < QPB * 8) {
        s_key[tid >> 3][tid & 7] =
            ((unsigned long long)0x7F7FFFFFull << 32)
            | (unsigned)(i0 + (tid >> 3));
    }
    __syncthreads();

    const int i  = i0 + qb;
    const float xi = xb[3 * i + 0], yi = xb[3 * i + 1], zi = xb[3 * i + 2];

    int cx = min(max((int)(xi * 10.0f), 0), GRIDR - 1);
    int cy = min(max((int)(yi * 10.0f), 0), GRIDR - 1);
    int cz = min(max((int)(zi * 10.0f), 0), GRIDR - 1);
    int ax0 = max(cx - 1, 0), ax1 = min(cx + 1, GRIDR - 1);
    int ay0 = max(cy - 1, 0), ay1 = min(cy + 1, GRIDR - 1);
    int az0 = max(cz - 1, 0), az1 = min(cz + 1, GRIDR - 1);
    int ny = ay1 - ay0 + 1;
    int ns = (ax1 - ax0 + 1) * ny;           // 4..9 spans

    const unsigned hm = 0xFFFFu << (h * 16);
    const int sbase = b * (NCELL + 1);
    const float4* __restrict__ srt = g_sorted + (size_t)b * NMAX;

    int rs = 0, re = 0;
    if (lane16 < ns) {
        int dxy = lane16 / ny;
        int rowc = ((ax0 + dxy) * GRIDR + (ay0 + lane16 - dxy * ny)) * GRIDR;
        rs = g_start[sbase + rowc + az0];
        re = g_start[sbase + rowc + az1 + 1];
    }

    for (int sp = strip; sp < ns; sp += 2) {
        int s0 = __shfl_sync(hm, rs, sp, 16);
        int e0 = __shfl_sync(hm, re, sp, 16);
        for (int k = s0 + lane16; k < e0; k += 16) {
            float4 p = srt[k];
            float dx = p.x - xi;
            float dy = p.y - yi;
            float dz = p.z - zi;
            if (fabsf(dx) < PRADIUS && fabsf(dy) < PRADIUS &&
                fabsf(dz) < PRADIUS) {
                unsigned j = (unsigned)__float_as_int(p.w);
                float d = __fadd_rn(
                    __fadd_rn(__fmul_rn(dx, dx), __fmul_rn(dy, dy)),
                    __fmul_rn(dz, dz));
                unsigned long long ck =
                    ((unsigned long long)(unsigned)__float_as_int(d) << 32) | j;
                int oct = ((dx > 0.0f) ? 4 : 0) |
                          ((dy > 0.0f) ? 2 : 0) |
                          ((dz > 0.0f) ? 1 : 0);
                atomicMin(&s_key[qb][oct], ck);
            }
        }
    }
    __syncthreads();

    // publish winners: 64 contiguous idx floats per block
    if (tid < QPB * 8) {
        int j = (int)(unsigned)(s_key[tid >> 3][tid & 7] & 0xFFFFFFFFull);
        s_jj[tid >> 3][tid & 7] = j;
        idx_f[(size_t)w0b * 8 + tid] = (float)j;
    }
    __syncthreads();

    // ================= gather phase (R6/R8): warp w owns query w0b+w ======
    const int iq = i0 + w;

    if (lane < 24) {
        int o = lane / 3;
        int c = lane - o * 3;
        int jj = s_jj[w][o];
        float v = xb[3 * jj + c] - xb[3 * iq + c];
        s_stage[w][o * FROW + c] = v;
        s_gx[w][lane] = v;
    }

    const float4* __restrict__ pb4 =
        (const float4*)(pts + (size_t)b * N * CFEAT);
    #pragma unroll
    for (int t0 = 0; t0 < 4; t0++) {
        int t  = lane + t0 * 32;     // 0..127
        int o  = t >> 4;
        int q  = t & 15;
        int jj = s_jj[w][o];
        float4 f4 = pb4[(size_t)jj * 16 + q];
        int basei = o * FROW + 3 + q * 4;
        s_stage[w][basei + 0] = f4.x;
        s_stage[w][basei + 1] = f4.y;
        s_stage[w][basei + 2] = f4.z;
        s_stage[w][basei + 3] = f4.w;
    }
    __syncwarp();

    float4*       gpo = (float4*)(gp + (size_t)(w0b + w) * GPROW);
    const float4* st4 = (const float4*)s_stage[w];
    #pragma unroll
    for (int f = lane; f < GPROW / 4; f += 32)
        gpo[f] = st4[f];
    if (lane < 6)
        ((float4*)(gxyz + (size_t)(w0b + w) * 24))[lane] =
            ((const float4*)s_gx[w])[lane];

    // ================= replay-safe reset =================
    __syncthreads();
    if (tid == 0) {
        int r = atomicAdd(&g_retire, 1);
        if (r == (int)gridDim.x - 1) {
            g_retire = 0;
            g_flag   = 0;
            __threadfence();
        }
    }
}

extern "C" void kernel_launch(void* const* d_in, const int* in_sizes, int n_in,
                              void* d_out, int out_size) {
    const float* xyz = (const float*)d_in[0];
    const float* pts = (const float*)d_in[1];
    float* out = (float*)d_out;

    int BN = in_sizes[0] / 3;       // B*N = 8192
    int B  = 2;
    int N  = BN / B;                // 4096

    size_t nG = (size_t)BN * 8;
    float* gxyz  = out;
    float* gp    = out + nG * 3;
    float* idx_f = out + nG * 3 + nG * (size_t)FROW;

    k_fused<<<(BN + QPB - 1) / QPB, QPB * 32>>>(
        xyz, pts, gxyz, gp, idx_f, B, N);
}

// round 12
// speedup vs baseline: 1.0140x; 1.0140x over previous
#include <cuda_runtime.h>
#include <float.h>

// ---------------------------------------------------------------------------
// PointSIFT select_cube + group, fused 2-kernel pipeline (R8 structure).
//   k_build: per-batch block; smem histogram + warp-shuffle scan + scatter
//            (counting sort on 10^3 grid, cell size == radius).
//   k_query_gather: block = 256 threads = 8 queries.
//     Search: each query served by TWO 16-lane strips in two paired warps
//       (z-spans split by parity); winners merged via smem atomicMin on
//       64-bit (dist_bits<<32 | j) keys (exact reference semantics:
//       unfused fp32 dist, min-dist then min-j tie-break).
//     R11: per-PAIR named barriers (bar.sync id,64) instead of block-wide
//       __syncthreads — fast pairs proceed to their gather while slow pairs
//       still search; block barrier coupling removed.
//     Gather: warp q owns query q; float4 feature loads staged in smem,
//       write-out as aligned float4 stores.
//
// Output layout (float32, reference return order):
//   [0 .. BN*8*3)             grouped_xyz   [B,N,8,3]
//   [.. +BN*8*(3+C))          grouped_points[B,N,8,3+C]
//   [.. +BN*8)                idx (int32 cast to float) [B,N,8]
// ---------------------------------------------------------------------------

#define GRIDR   10
#define NCELL   (GRIDR*GRIDR*GRIDR)   // 1000
#define BMAX    2
#define NMAX    4096
#define PRADIUS 0.1f
#define QPB     8                     // queries per block == warps per block
#define CFEAT   64
#define FROW    (3 + CFEAT)           // 67
#define GPROW   (8 * FROW)            // 536 floats per query row

__device__ int    g_start [BMAX * (NCELL + 1)];
__device__ float4 g_sorted[BMAX * NMAX];   // x,y,z, w = bitcast(orig index)

__device__ __forceinline__ int cell_of(float x, float y, float z) {
    int cx = (int)(x * 10.0f); cx = min(max(cx, 0), GRIDR - 1);
    int cy = (int)(y * 10.0f); cy = min(max(cy, 0), GRIDR - 1);
    int cz = (int)(z * 10.0f); cz = min(max(cz, 0), GRIDR - 1);
    return (cx * GRIDR + cy) * GRIDR + cz;
}

__device__ __forceinline__ void pair_bar(int id) {
    asm volatile("bar.sync %0, 64;" :: "r"(id) : "memory");
}

// One block per batch. Histogram + warp-shuffle scan + scatter via smem.
__global__ __launch_bounds__(1024) void k_build(const float* __restrict__ xyz,
                                                int N) {
    __shared__ int s_cur [NCELL];
    __shared__ int s_wsum[32];

    int b   = blockIdx.x;
    int tid = threadIdx.x;
    int wid = tid >> 5;
    int lid = tid & 31;
    const float* xb = xyz + (size_t)b * N * 3;

    if (tid < NCELL) s_cur[tid] = 0;
    __syncthreads();

    const int PT = (NMAX + 1023) / 1024;   // 4
    float px[PT], py[PT], pz[PT];
    int   pc[PT];
    #pragma unroll
    for (int p = 0; p < PT; p++) {
        int i = tid + p * 1024;
        pc[p] = -1;
        if (i < N) {
            px[p] = xb[3 * i + 0];
            py[p] = xb[3 * i + 1];
            pz[p] = xb[3 * i + 2];
            pc[p] = cell_of(px[p], py[p], pz[p]);
            atomicAdd(&s_cur[pc[p]], 1);
        }
    }
    __syncthreads();

    int v = (tid < NCELL) ? s_cur[tid] : 0;
    int x = v;
    #pragma unroll
    for (int off = 1; off < 32; off <<= 1) {
        int y = __shfl_up_sync(0xFFFFFFFFu, x, off);
        if (lid >= off) x += y;
    }
    if (lid == 31) s_wsum[wid] = x;
    __syncthreads();
    if (wid == 0) {
        int y = s_wsum[lid];
        #pragma unroll
        for (int off = 1; off < 32; off <<= 1) {
            int z2 = __shfl_up_sync(0xFFFFFFFFu, y, off);
            if (lid >= off) y += z2;
        }
        s_wsum[lid] = y;
    }
    __syncthreads();
    int incl = x + (wid > 0 ? s_wsum[wid - 1] : 0);
    if (tid < NCELL) {
        int excl = incl - v;
        g_start[b * (NCELL + 1) + tid] = excl;
        s_cur[tid] = excl;
        if (tid == NCELL - 1)
            g_start[b * (NCELL + 1) + NCELL] = incl;
    }
    __syncthreads();

    float4* dst = g_sorted + (size_t)b * NMAX;
    #pragma unroll
    for (int p = 0; p < PT; p++) {
        if (pc[p] >= 0) {
            int pos = atomicAdd(&s_cur[pc[p]], 1);
            int i = tid + p * 1024;
            dst[pos] = make_float4(px[p], py[p], pz[p], __int_as_float(i));
        }
    }
}

// 8 queries/block; 2 strips x 16 lanes per query; pair-scoped barriers.
__global__ __launch_bounds__(QPB * 32)
void k_query_gather(const float* __restrict__ xyz,
                    const float* __restrict__ pts,
                    float* __restrict__ gxyz,
                    float* __restrict__ gp,
                    float* __restrict__ idx_f,
                    int B, int N) {
    __shared__ unsigned long long s_key [QPB][8];
    __shared__ int                s_jj  [QPB][8];
    __shared__ alignas(16) float  s_stage[QPB][GPROW];  // 8 x 536
    __shared__ alignas(16) float  s_gx   [QPB][24];

    const int tid    = threadIdx.x;
    const int w      = tid >> 5;
    const int lane   = tid & 31;
    const int h      = lane >> 4;          // half-warp id
    const int lane16 = lane & 15;
    const int strip  = w & 1;              // span-parity strip
    const int pair   = w >> 1;             // warp pair 0..3
    const int qb     = (w & ~1) + h;       // query slot in block (0..7)
    const int w0b    = blockIdx.x * QPB;   // first global query of block
    const int barid  = 1 + pair;           // named barrier id (1..4)

    // block never straddles a batch (N % QPB == 0)
    const int b  = w0b / N;
    const int i0 = w0b - b * N;
    const float* xb = xyz + (size_t)b * N * 3;

    // init the pair's two key rows (even warp, lanes 0..15)
    if (strip == 0 && lane < 16) {
        int q = (pair << 1) + (lane >> 3);
        s_key[q][lane & 7] =
            ((unsigned long long)0x7F7FFFFFull << 32) | (unsigned)(i0 + q);
    }
    pair_bar(barid);

    // ---------------- search ----------------
    const int i  = i0 + qb;
    const float xi = xb[3 * i + 0], yi = xb[3 * i + 1], zi = xb[3 * i + 2];

    int cx = min(max((int)(xi * 10.0f), 0), GRIDR - 1);
    int cy = min(max((int)(yi * 10.0f), 0), GRIDR - 1);
    int cz = min(max((int)(zi * 10.0f), 0), GRIDR - 1);
    int ax0 = max(cx - 1, 0), ax1 = min(cx + 1, GRIDR - 1);
    int ay0 = max(cy - 1, 0), ay1 = min(cy + 1, GRIDR - 1);
    int az0 = max(cz - 1, 0), az1 = min(cz + 1, GRIDR - 1);
    int ny = ay1 - ay0 + 1;
    int ns = (ax1 - ax0 + 1) * ny;         // 4..9 spans

    const unsigned hm = 0xFFFFu << (h * 16);
    const int sbase = b * (NCELL + 1);
    const float4* __restrict__ srt = g_sorted + (size_t)b * NMAX;

    // prefetch all span ranges in parallel (lanes 0..ns-1 of this half)
    int rs = 0, re = 0;
    if (lane16 < ns) {
        int dxy = lane16 / ny;
        int rowc = ((ax0 + dxy) * GRIDR + (ay0 + lane16 - dxy * ny)) * GRIDR;
        rs = g_start[sbase + rowc + az0];
        re = g_start[sbase + rowc + az1 + 1];
    }

    for (int sp = strip; sp < ns; sp += 2) {
        int s0 = __shfl_sync(hm, rs, sp, 16);
        int e0 = __shfl_sync(hm, re, sp, 16);
        for (int k = s0 + lane16; k < e0; k += 16) {
            float4 p = srt[k];
            float dx = p.x - xi;
            float dy = p.y - yi;
            float dz = p.z - zi;
            // bitwise & : one predicate, no short-circuit branch chain
            if ((fabsf(dx) < PRADIUS) & (fabsf(dy) < PRADIUS) &
                (fabsf(dz) < PRADIUS)) {
                unsigned j = (unsigned)__float_as_int(p.w);
                float d = __fadd_rn(
                    __fadd_rn(__fmul_rn(dx, dx), __fmul_rn(dy, dy)),
                    __fmul_rn(dz, dz));
                unsigned long long ck =
                    ((unsigned long long)(unsigned)__float_as_int(d) << 32) | j;
                int oct = ((dx > 0.0f) ? 4 : 0) |
                          ((dy > 0.0f) ? 2 : 0) |
                          ((dz > 0.0f) ? 1 : 0);
                atomicMin(&s_key[qb][oct], ck);
            }
        }
    }
    pair_bar(barid);

    // publish winners for the pair: 16 contiguous idx floats
    if (strip == 0 && lane < 16) {
        int q = (pair << 1) + (lane >> 3);
        int j = (int)(unsigned)(s_key[q][lane & 7] & 0xFFFFFFFFull);
        s_jj[q][lane & 7] = j;
        idx_f[(size_t)(w0b + (pair << 1)) * 8 + lane] = (float)j;
    }
    pair_bar(barid);

    // ---------------- gather: warp w owns query (w0b + w) ----------------
    const int iq = i0 + w;

    if (lane < 24) {
        int o = lane / 3;
        int c = lane - o * 3;
        int jj = s_jj[w][o];
        float v = xb[3 * jj + c] - xb[3 * iq + c];
        s_stage[w][o * FROW + c] = v;
        s_gx[w][lane] = v;
    }

    const float4* __restrict__ pb4 =
        (const float4*)(pts + (size_t)b * N * CFEAT);
    #pragma unroll
    for (int t0 = 0; t0 < 4; t0++) {
        int t  = lane + t0 * 32;     // 0..127
        int o  = t >> 4;
        int q  = t & 15;
        int jj = s_jj[w][o];
        float4 f4 = pb4[(size_t)jj * 16 + q];
        int base = o * FROW + 3 + q * 4;
        s_stage[w][base + 0] = f4.x;
        s_stage[w][base + 1] = f4.y;
        s_stage[w][base + 2] = f4.z;
        s_stage[w][base + 3] = f4.w;
    }
    __syncwarp();

    // write-out: 536 floats = 134 aligned float4 per query row
    float4*       gpo = (float4*)(gp + (size_t)(w0b + w) * GPROW);
    const float4* st4 = (const float4*)s_stage[w];
    #pragma unroll
    for (int f = lane; f < GPROW / 4; f += 32)
        gpo[f] = st4[f];
    if (lane < 6)
        ((float4*)(gxyz + (size_t)(w0b + w) * 24))[lane] =
            ((const float4*)s_gx[w])[lane];
}

extern "C" void kernel_launch(void* const* d_in, const int* in_sizes, int n_in,
                              void* d_out, int out_size) {
    const float* xyz = (const float*)d_in[0];
    const float* pts = (const float*)d_in[1];
    float* out = (float*)d_out;

    int BN = in_sizes[0] / 3;       // B*N = 8192
    int B  = 2;
    int N  = BN / B;                // 4096

    size_t nG = (size_t)BN * 8;
    float* gxyz  = out;
    float* gp    = out + nG * 3;
    float* idx_f = out + nG * 3 + nG * (size_t)FROW;

    k_build<<<B, 1024>>>(xyz, N);
    k_query_gather<<<(BN + QPB - 1) / QPB, QPB * 32>>>(
        xyz, pts, gxyz, gp, idx_f, B, N);
}

// round 13
// speedup vs baseline: 1.2080x; 1.1913x over previous
#include <cuda_runtime.h>
#include <float.h>

// ---------------------------------------------------------------------------
// PointSIFT select_cube + group, fused 2-kernel pipeline (R8 structure).
//   k_build: per-batch block; smem histogram + warp-shuffle scan + scatter
//            (counting sort on 10^3 grid, cell size == radius).
//   k_query_gather (R12): queries processed in CELL-SORTED order — block's 8
//     queries come from consecutive g_sorted slots, so all 16 strips of a
//     block touch (nearly) the same 27-cell neighborhood -> candidate loads
//     hit L1 instead of L2. Original index rides in .w for output addressing.
//     Search: 2 strips x 16 lanes per query (z-spans split by parity),
//       winners via block-smem atomicMin on 64-bit (dist_bits<<32 | j) keys
//       (exact reference semantics: unfused fp32 dist, min-dist then min-j).
//     Gather: warp q owns query q; float4 feature loads staged in smem,
//       write-out as aligned float4 stores to the query's original row.
//
// Output layout (float32, reference return order):
//   [0 .. BN*8*3)             grouped_xyz   [B,N,8,3]
//   [.. +BN*8*(3+C))          grouped_points[B,N,8,3+C]
//   [.. +BN*8)                idx (int32 cast to float) [B,N,8]
// ---------------------------------------------------------------------------

#define GRIDR   10
#define NCELL   (GRIDR*GRIDR*GRIDR)   // 1000
#define BMAX    2
#define NMAX    4096
#define PRADIUS 0.1f
#define QPB     8                     // queries per block == warps per block
#define CFEAT   64
#define FROW    (3 + CFEAT)           // 67
#define GPROW   (8 * FROW)            // 536 floats per query row

__device__ int    g_start [BMAX * (NCELL + 1)];
__device__ float4 g_sorted[BMAX * NMAX];   // x,y,z, w = bitcast(orig index)

__device__ __forceinline__ int cell_of(float x, float y, float z) {
    int cx = (int)(x * 10.0f); cx = min(max(cx, 0), GRIDR - 1);
    int cy = (int)(y * 10.0f); cy = min(max(cy, 0), GRIDR - 1);
    int cz = (int)(z * 10.0f); cz = min(max(cz, 0), GRIDR - 1);
    return (cx * GRIDR + cy) * GRIDR + cz;
}

// One block per batch. Histogram + warp-shuffle scan + scatter via smem.
__global__ __launch_bounds__(1024) void k_build(const float* __restrict__ xyz,
                                                int N) {
    __shared__ int s_cur [NCELL];
    __shared__ int s_wsum[32];

    int b   = blockIdx.x;
    int tid = threadIdx.x;
    int wid = tid >> 5;
    int lid = tid & 31;
    const float* xb = xyz + (size_t)b * N * 3;

    if (tid < NCELL) s_cur[tid] = 0;
    __syncthreads();

    const int PT = (NMAX + 1023) / 1024;   // 4
    float px[PT], py[PT], pz[PT];
    int   pc[PT];
    #pragma unroll
    for (int p = 0; p < PT; p++) {
        int i = tid + p * 1024;
        pc[p] = -1;
        if (i < N) {
            px[p] = xb[3 * i + 0];
            py[p] = xb[3 * i + 1];
            pz[p] = xb[3 * i + 2];
            pc[p] = cell_of(px[p], py[p], pz[p]);
            atomicAdd(&s_cur[pc[p]], 1);
        }
    }
    __syncthreads();

    int v = (tid < NCELL) ? s_cur[tid] : 0;
    int x = v;
    #pragma unroll
    for (int off = 1; off < 32; off <<= 1) {
        int y = __shfl_up_sync(0xFFFFFFFFu, x, off);
        if (lid >= off) x += y;
    }
    if (lid == 31) s_wsum[wid] = x;
    __syncthreads();
    if (wid == 0) {
        int y = s_wsum[lid];
        #pragma unroll
        for (int off = 1; off < 32; off <<= 1) {
            int z2 = __shfl_up_sync(0xFFFFFFFFu, y, off);
            if (lid >= off) y += z2;
        }
        s_wsum[lid] = y;
    }
    __syncthreads();
    int incl = x + (wid > 0 ? s_wsum[wid - 1] : 0);
    if (tid < NCELL) {
        int excl = incl - v;
        g_start[b * (NCELL + 1) + tid] = excl;
        s_cur[tid] = excl;
        if (tid == NCELL - 1)
            g_start[b * (NCELL + 1) + NCELL] = incl;
    }
    __syncthreads();

    float4* dst = g_sorted + (size_t)b * NMAX;
    #pragma unroll
    for (int p = 0; p < PT; p++) {
        if (pc[p] >= 0) {
            int pos = atomicAdd(&s_cur[pc[p]], 1);
            int i = tid + p * 1024;
            dst[pos] = make_float4(px[p], py[p], pz[p], __int_as_float(i));
        }
    }
}

// 8 sorted-order queries/block; 2 strips x 16 lanes per query.
__global__ __launch_bounds__(QPB * 32)
void k_query_gather(const float* __restrict__ xyz,
                    const float* __restrict__ pts,
                    float* __restrict__ gxyz,
                    float* __restrict__ gp,
                    float* __restrict__ idx_f,
                    int B, int N) {
    __shared__ unsigned long long s_key [QPB][8];
    __shared__ int                s_jj  [QPB][8];
    __shared__ alignas(16) float  s_stage[QPB][GPROW];  // 8 x 536
    __shared__ alignas(16) float  s_gx   [QPB][24];

    const int tid    = threadIdx.x;
    const int w      = tid >> 5;
    const int lane   = tid & 31;
    const int h      = lane >> 4;          // half-warp id
    const int lane16 = lane & 15;
    const int strip  = w & 1;              // span-parity strip
    const int qb     = (w & ~1) + h;       // query slot in block (0..7)

    const int bpb = N / QPB;               // blocks per batch (512)
    const int b   = blockIdx.x / bpb;
    const int q0  = (blockIdx.x - b * bpb) * QPB;  // sorted-array offset

    const float* xb = xyz + (size_t)b * N * 3;
    const float4* __restrict__ srt = g_sorted + (size_t)b * NMAX;

    // seed winner keys: (FLT_MAX, original self index)
    if (tid < QPB * 8) {
        int q  = tid >> 3;
        int iq = __float_as_int(srt[q0 + q].w);
        s_key[q][tid & 7] =
            ((unsigned long long)0x7F7FFFFFull << 32) | (unsigned)iq;
    }
    __syncthreads();

    // ---------------- search (query slot qb, sorted order) ----------------
    const float4 sq = srt[q0 + qb];
    const float xi = sq.x, yi = sq.y, zi = sq.z;

    int cx = min(max((int)(xi * 10.0f), 0), GRIDR - 1);
    int cy = min(max((int)(yi * 10.0f), 0), GRIDR - 1);
    int cz = min(max((int)(zi * 10.0f), 0), GRIDR - 1);
    int ax0 = max(cx - 1, 0), ax1 = min(cx + 1, GRIDR - 1);
    int ay0 = max(cy - 1, 0), ay1 = min(cy + 1, GRIDR - 1);
    int az0 = max(cz - 1, 0), az1 = min(cz + 1, GRIDR - 1);
    int ny = ay1 - ay0 + 1;
    int ns = (ax1 - ax0 + 1) * ny;         // 4..9 spans

    const unsigned hm = 0xFFFFu << (h * 16);
    const int sbase = b * (NCELL + 1);

    // prefetch all span ranges in parallel (lanes 0..ns-1 of this half)
    int rs = 0, re = 0;
    if (lane16 < ns) {
        int dxy = lane16 / ny;
        int rowc = ((ax0 + dxy) * GRIDR + (ay0 + lane16 - dxy * ny)) * GRIDR;
        rs = g_start[sbase + rowc + az0];
        re = g_start[sbase + rowc + az1 + 1];
    }

    for (int sp = strip; sp < ns; sp += 2) {
        int s0 = __shfl_sync(hm, rs, sp, 16);
        int e0 = __shfl_sync(hm, re, sp, 16);
        for (int k = s0 + lane16; k < e0; k += 16) {
            float4 p = srt[k];
            float dx = p.x - xi;
            float dy = p.y - yi;
            float dz = p.z - zi;
            if ((fabsf(dx) < PRADIUS) & (fabsf(dy) < PRADIUS) &
                (fabsf(dz) < PRADIUS)) {
                unsigned j = (unsigned)__float_as_int(p.w);
                float d = __fadd_rn(
                    __fadd_rn(__fmul_rn(dx, dx), __fmul_rn(dy, dy)),
                    __fmul_rn(dz, dz));
                unsigned long long ck =
                    ((unsigned long long)(unsigned)__float_as_int(d) << 32) | j;
                int oct = ((dx > 0.0f) ? 4 : 0) |
                          ((dy > 0.0f) ? 2 : 0) |
                          ((dz > 0.0f) ? 1 : 0);
                atomicMin(&s_key[qb][oct], ck);
            }
        }
    }
    __syncthreads();

    // publish winners into s_jj (idx written per-query below)
    if (tid < QPB * 8) {
        s_jj[tid >> 3][tid & 7] =
            (int)(unsigned)(s_key[tid >> 3][tid & 7] & 0xFFFFFFFFull);
    }
    __syncthreads();

    // ---------------- gather: warp w owns sorted query (q0 + w) -----------
    const float4 mq = srt[q0 + w];
    const int    iw = __float_as_int(mq.w);      // original index -> out row
    const size_t row = (size_t)b * N + iw;

    if (lane < 8)
        idx_f[row * 8 + lane] = (float)s_jj[w][lane];

    // centered xyz: 24 values (lanes 0..23)
    if (lane < 24) {
        int o = lane / 3;
        int c = lane - o * 3;
        int jj = s_jj[w][o];
        float own = (c == 0) ? mq.x : (c == 1) ? mq.y : mq.z;
        float v = xb[3 * jj + c] - own;
        s_stage[w][o * FROW + c] = v;
        s_gx[w][lane] = v;
    }

    // features: 8 octants x 16 float4 = 128 vector loads, 4 dense iterations
    const float4* __restrict__ pb4 =
        (const float4*)(pts + (size_t)b * N * CFEAT);
    #pragma unroll
    for (int t0 = 0; t0 < 4; t0++) {
        int t  = lane + t0 * 32;     // 0..127
        int o  = t >> 4;
        int q  = t & 15;
        int jj = s_jj[w][o];
        float4 f4 = pb4[(size_t)jj * 16 + q];
        int base = o * FROW + 3 + q * 4;
        s_stage[w][base + 0] = f4.x;
        s_stage[w][base + 1] = f4.y;
        s_stage[w][base + 2] = f4.z;
        s_stage[w][base + 3] = f4.w;
    }
    __syncwarp();

    // write-out: 536 floats = 134 aligned float4 to the original row
    float4*       gpo = (float4*)(gp + row * GPROW);
    const float4* st4 = (const float4*)s_stage[w];
    #pragma unroll
    for (int f = lane; f < GPROW / 4; f += 32)
        gpo[f] = st4[f];
    if (lane < 6)
        ((float4*)(gxyz + row * 24))[lane] =
            ((const float4*)s_gx[w])[lane];
}

extern "C" void kernel_launch(void* const* d_in, const int* in_sizes, int n_in,
                              void* d_out, int out_size) {
    const float* xyz = (const float*)d_in[0];
    const float* pts = (const float*)d_in[1];
    float* out = (float*)d_out;

    int BN = in_sizes[0] / 3;       // B*N = 8192
    int B  = 2;
    int N  = BN / B;                // 4096

    size_t nG = (size_t)BN * 8;
    float* gxyz  = out;
    float* gp    = out + nG * 3;
    float* idx_f = out + nG * 3 + nG * (size_t)FROW;

    k_build<<<B, 1024>>>(xyz, N);
    k_query_gather<<<(BN + QPB - 1) / QPB, QPB * 32>>>(
        xyz, pts, gxyz, gp, idx_f, B, N);
}